// round 7
// baseline (speedup 1.0000x reference)
#include <cuda_runtime.h>
#include <cstdint>
#include <cstddef>
#include <climits>

#define NPTS     8192
#define BATCH    8
#define MSEL     4096        // ceil(0.5 * 8192)
#define NTHREADS 1024
#define PPT      8           // points per thread
// smem floats: packed pos pairs [NPTS*6] + warp max [2*32] + gidx [2] + pad [2] + idx list [MSEL]
#define SMEM_FLOATS (NPTS * 6 + 64 + 4 + MSEL)
#define SMEM_BYTES  (SMEM_FLOATS * 4)

// Selected indices, produced by FPS kernel, consumed by gather kernel.
__device__ int g_sel_idx[BATCH * MSEL];

// ---------------- f32x2 packed helpers (sm_100+) ----------------
__device__ __forceinline__ unsigned long long pack2(float lo, float hi) {
    unsigned long long r;
    asm("mov.b64 %0, {%1, %2};" : "=l"(r) : "f"(lo), "f"(hi));
    return r;
}
__device__ __forceinline__ void unpack2(unsigned long long v, float& lo, float& hi) {
    asm("mov.b64 {%0, %1}, %2;" : "=f"(lo), "=f"(hi) : "l"(v));
}
__device__ __forceinline__ unsigned long long add2(unsigned long long a, unsigned long long b) {
    unsigned long long r;
    asm("add.rn.f32x2 %0, %1, %2;" : "=l"(r) : "l"(a), "l"(b));
    return r;
}
__device__ __forceinline__ unsigned long long mul2(unsigned long long a, unsigned long long b) {
    unsigned long long r;
    asm("mul.rn.f32x2 %0, %1, %2;" : "=l"(r) : "l"(a), "l"(b));
    return r;
}

extern __shared__ float smem[];

// ---------------- FPS kernel: one CTA per batch ----------------
__global__ __launch_bounds__(NTHREADS, 1)
void fps_kernel(const float* __restrict__ points, float* __restrict__ dp_out)
{
    float*    s_pos2 = smem;                          // [NPTS*6] {x,x}{y,y}{z,z} per point
    unsigned* s_wmax = (unsigned*)(smem + NPTS * 6);  // [2][32] per-warp max bits
    int*      s_gidx = (int*)(smem + NPTS * 6 + 64);  // [2] global argmax (atomicMin)
    int*      s_idx  = (int*)(smem + NPTS * 6 + 68);  // [MSEL] selected indices

    const int b    = blockIdx.x;
    const int tid  = threadIdx.x;
    const int lane = tid & 31;
    const int warp = tid >> 5;
    const float* p = points + (size_t)b * NPTS * 3;

    // Stage duplicated point pairs to shared (coalesced gmem reads).
    for (int k = tid; k < NPTS * 3; k += NTHREADS) {
        float v = p[k];
        int   i = k / 3, c = k - 3 * i;
        s_pos2[6 * i + 2 * c]     = v;
        s_pos2[6 * i + 2 * c + 1] = v;
    }
    if (tid == 0) {
        s_gidx[0] = INT_MAX;
        s_gidx[1] = INT_MAX;
        s_idx[0]  = 0;
    }
    __syncthreads();

    // Register-resident NEGATED coords: pair j holds ids 2j*1024+tid (lo), (2j+1)*1024+tid (hi).
    unsigned long long NX[PPT / 2], NY[PPT / 2], NZ[PPT / 2];
    float mind[PPT];
#pragma unroll
    for (int i = 0; i < PPT; i++) mind[i] = 1e10f;
#pragma unroll
    for (int j = 0; j < PPT / 2; j++) {
        int i0 = (2 * j) * NTHREADS + tid;
        int i1 = (2 * j + 1) * NTHREADS + tid;
        NX[j] = pack2(-s_pos2[6 * i0 + 0], -s_pos2[6 * i1 + 0]);
        NY[j] = pack2(-s_pos2[6 * i0 + 2], -s_pos2[6 * i1 + 2]);
        NZ[j] = pack2(-s_pos2[6 * i0 + 4], -s_pos2[6 * i1 + 4]);
    }

    int gidx = 0;  // step 0: deterministic start at index 0
    int buf  = 0;

    for (int step = 1; step < MSEL; ++step) {
        // Broadcast the selected point as pre-duplicated 64-bit pairs (3x LDS.64).
        const unsigned long long* lp =
            (const unsigned long long*)(s_pos2 + 6 * gidx);
        unsigned long long lx2 = lp[0];
        unsigned long long ly2 = lp[1];
        unsigned long long lz2 = lp[2];

        // XLA-exact: (-x + lx)^2 == (x - lx)^2 bit-exactly; every op rounded, no FMA.
#pragma unroll
        for (int j = 0; j < PPT / 2; j++) {
            unsigned long long dx = add2(NX[j], lx2);
            unsigned long long dy = add2(NY[j], ly2);
            unsigned long long dz = add2(NZ[j], lz2);
            unsigned long long sx = mul2(dx, dx);
            unsigned long long sy = mul2(dy, dy);
            unsigned long long sz = mul2(dz, dz);
            unsigned long long dd = add2(add2(sx, sy), sz);
            float d0, d1;
            unpack2(dd, d0, d1);
            mind[2 * j]     = fminf(mind[2 * j], d0);
            mind[2 * j + 1] = fminf(mind[2 * j + 1], d1);
        }

        // Max-tree over the 8 running minima (depth 3).
        float m01 = fmaxf(mind[0], mind[1]);
        float m23 = fmaxf(mind[2], mind[3]);
        float m45 = fmaxf(mind[4], mind[5]);
        float m67 = fmaxf(mind[6], mind[7]);
        float vmax = fmaxf(fmaxf(m01, m23), fmaxf(m45, m67));

        // Stage A: value-only warp max.
        unsigned vb   = __float_as_uint(vmax);  // nonneg floats: uint order == float order
        unsigned wmax = __reduce_max_sync(0xffffffffu, vb);
        if (lane == 0) s_wmax[buf * 32 + warp] = wmax;
        __syncthreads();  // bar A

        // Stage B: every warp reduces the 32 warp maxima.
        unsigned gmax = __reduce_max_sync(0xffffffffu, s_wmax[buf * 32 + lane]);

        // Only global-max owners (≈1 warp) search + publish lowest index.
        if (vb == gmax) {
            int cand = INT_MAX;
#pragma unroll
            for (int i = PPT - 1; i >= 0; i--)
                if (__float_as_uint(mind[i]) == gmax) cand = i * NTHREADS + tid;
            atomicMin(&s_gidx[buf], cand);
        }
        if (tid == 0) s_gidx[buf ^ 1] = INT_MAX;  // reset next buffer
        __syncthreads();  // bar B

        gidx = s_gidx[buf];
        if (tid == 0) s_idx[step] = gidx;
        buf ^= 1;
    }
    __syncthreads();  // s_idx complete

    // Batched writeout of indices + selected points (off the critical loop).
    for (int r = tid; r < MSEL; r += NTHREADS) {
        int id = s_idx[r];
        g_sel_idx[b * MSEL + r] = id;
        size_t o = ((size_t)b * MSEL + r) * 3;
        dp_out[o + 0] = s_pos2[6 * id + 0];
        dp_out[o + 1] = s_pos2[6 * id + 2];
        dp_out[o + 2] = s_pos2[6 * id + 4];
    }
}

// ---------------- Feature gather: [B, m, 256] float32 ----------------
__global__ void gather_kernel(const float* __restrict__ feat, float* __restrict__ df_out)
{
    // 256 threads/block -> 4 rows/block, 64 threads (float4 x 64 = 256 floats) per row.
    int r = blockIdx.x * 4 + (threadIdx.x >> 6);
    int c = threadIdx.x & 63;
    int b = r >> 12;  // r / 4096
    int id = g_sel_idx[r];
    const float4* src = (const float4*)(feat + ((size_t)b * NPTS + id) * 256);
    float4 v = src[c];
    ((float4*)df_out)[(size_t)r * 64 + c] = v;
}

extern "C" void kernel_launch(void* const* d_in, const int* in_sizes, int n_in,
                              void* d_out, int out_size)
{
    (void)n_in; (void)out_size;
    const float* points;
    const float* feats;
    if (in_sizes[0] == BATCH * NPTS * 3) {
        points = (const float*)d_in[0];
        feats  = (const float*)d_in[1];
    } else {
        points = (const float*)d_in[1];
        feats  = (const float*)d_in[0];
    }

    float* out = (float*)d_out;
    float* dp  = out;                              // [B, m, 3]
    float* df  = out + (size_t)BATCH * MSEL * 3;   // [B, m, 256]

    cudaFuncSetAttribute(fps_kernel, cudaFuncAttributeMaxDynamicSharedMemorySize,
                         SMEM_BYTES);
    fps_kernel<<<BATCH, NTHREADS, SMEM_BYTES>>>(points, dp);
    gather_kernel<<<(BATCH * MSEL) / 4, 256>>>(feats, df);
}